// round 3
// baseline (speedup 1.0000x reference)
#include <cuda_runtime.h>
#include <cstdint>

// Problem constants
#define B_    8
#define L_    4096
#define D_    384
#define DI_   768
#define S_    16
#define DTR_  24
#define NC_   40
#define MTOK  (B_*L_)          // 32768
#define XPD   (DTR_ + 2*S_)    // 56

// ---------------- scratch (device globals; no allocation allowed) ----------------
__device__ float g_xn  [(size_t)MTOK * D_];    // rmsnormed x           50 MB
__device__ float g_xp  [(size_t)MTOK * DI_];   // pre-conv branch      100 MB
__device__ float g_zs  [(size_t)MTOK * DI_];   // silu(z)              100 MB
__device__ float g_xc  [(size_t)MTOK * DI_];   // conv+silu            100 MB
__device__ float g_xdbl[(size_t)MTOK * XPD];   // [dt_r | B | C]         7 MB
__device__ float g_dt  [(size_t)MTOK * DI_];   // softplus dt          100 MB
__device__ float g_xbar[B_ * D_];              // sum_l x
__device__ float g_ybar[B_ * DI_];             // sum_l y_final

// ---------------- kernels ----------------

__global__ void k_zero_xbar() {
    int i = blockIdx.x * blockDim.x + threadIdx.x;
    if (i < B_ * D_) g_xbar[i] = 0.f;
}

// partial sums of x over l (per (b,d)); grid = B*64 blocks x 384 threads
__global__ void k_xbar(const float* __restrict__ x) {
    int b  = blockIdx.x >> 6;
    int l0 = (blockIdx.x & 63) * 64;
    int d  = threadIdx.x;
    const float* p = x + ((size_t)(b * L_ + l0)) * D_ + d;
    float s = 0.f;
    #pragma unroll 8
    for (int i = 0; i < 64; i++) s += p[(size_t)i * D_];
    atomicAdd(&g_xbar[b * D_ + d], s);
}

// RMSNorm: warp per row; grid 4096 x 256
__global__ void k_rmsnorm(const float* __restrict__ x, const float* __restrict__ ln_w) {
    int row  = blockIdx.x * (blockDim.x >> 5) + (threadIdx.x >> 5);
    int lane = threadIdx.x & 31;
    const float* rp = x + (size_t)row * D_;
    float v[12]; float s = 0.f;
    #pragma unroll
    for (int i = 0; i < 12; i++) { v[i] = rp[lane + i * 32]; s += v[i] * v[i]; }
    #pragma unroll
    for (int o = 16; o; o >>= 1) s += __shfl_xor_sync(0xffffffffu, s, o);
    float r = rsqrtf(s * (1.f / D_) + 1e-5f);
    float* op = g_xn + (size_t)row * D_;
    #pragma unroll
    for (int i = 0; i < 12; i++) op[lane + i * 32] = v[i] * r * ln_w[lane + i * 32];
}

// GEMM1: g_xn[M,384] @ W_in[384,1536] -> xp (cols<768), silu-> zs (cols>=768)
// 128x128x16 tile, 256 threads, 8x8 per thread
__global__ void __launch_bounds__(256) k_gemm1(const float* __restrict__ Win) {
    __shared__ float As[16][128];
    __shared__ float Bs[16][128];
    int tid = threadIdx.x;
    int tx = tid & 15, ty = tid >> 4;
    int m0 = blockIdx.y * 128, n0 = blockIdx.x * 128;
    float acc[8][8] = {};
    for (int k0 = 0; k0 < D_; k0 += 16) {
        #pragma unroll
        for (int i = 0; i < 2; i++) {
            int f4 = tid + i * 256;
            int row = f4 >> 2, kc = (f4 & 3) << 2;
            float4 v = *(const float4*)&g_xn[(size_t)(m0 + row) * D_ + k0 + kc];
            As[kc][row] = v.x; As[kc + 1][row] = v.y; As[kc + 2][row] = v.z; As[kc + 3][row] = v.w;
        }
        #pragma unroll
        for (int i = 0; i < 2; i++) {
            int f4 = tid + i * 256;
            int kr = f4 >> 5, nc = (f4 & 31) << 2;
            *(float4*)&Bs[kr][nc] = *(const float4*)&Win[(size_t)(k0 + kr) * (2 * DI_) + n0 + nc];
        }
        __syncthreads();
        #pragma unroll
        for (int kk = 0; kk < 16; kk++) {
            float a[8], b[8];
            *(float4*)(a)     = *(float4*)&As[kk][ty * 8];
            *(float4*)(a + 4) = *(float4*)&As[kk][ty * 8 + 4];
            *(float4*)(b)     = *(float4*)&Bs[kk][tx * 8];
            *(float4*)(b + 4) = *(float4*)&Bs[kk][tx * 8 + 4];
            #pragma unroll
            for (int i = 0; i < 8; i++)
                #pragma unroll
                for (int j = 0; j < 8; j++)
                    acc[i][j] = fmaf(a[i], b[j], acc[i][j]);
        }
        __syncthreads();
    }
    #pragma unroll
    for (int i = 0; i < 8; i++) {
        int m = m0 + ty * 8 + i;
        #pragma unroll
        for (int j = 0; j < 8; j++) {
            int n = n0 + tx * 8 + j;
            float v = acc[i][j];
            if (n < DI_) {
                g_xp[(size_t)m * DI_ + n] = v;
            } else {
                float sg = 1.f / (1.f + __expf(-v));
                g_zs[(size_t)m * DI_ + (n - DI_)] = v * sg;
            }
        }
    }
}

// causal depthwise conv K=4 + silu
__global__ void k_conv(const float* __restrict__ cw, const float* __restrict__ cb) {
    int idx = blockIdx.x * 256 + threadIdx.x;   // (b*L+l)*DI + di
    int di = idx % DI_;
    int ml = idx / DI_;
    int l  = ml & (L_ - 1);
    float w0 = cw[di * 4], w1 = cw[di * 4 + 1], w2 = cw[di * 4 + 2], w3 = cw[di * 4 + 3];
    const float* p = g_xp + (size_t)ml * DI_ + di;
    float s = cb[di] + w3 * p[0];
    if (l >= 1) s = fmaf(w2, p[-DI_], s);
    if (l >= 2) s = fmaf(w1, p[-2 * DI_], s);
    if (l >= 3) s = fmaf(w0, p[-3 * DI_], s);
    float sg = 1.f / (1.f + __expf(-s));
    g_xc[(size_t)ml * DI_ + di] = s * sg;
}

// x_dbl = xc[M,768] @ W_xproj[768,56] ; 64x64(56 valid)x32 tile, 4x4/thread
__global__ void __launch_bounds__(256) k_xproj(const float* __restrict__ Wx) {
    __shared__ float As[32][64];
    __shared__ float Bs[32][64];
    int tid = threadIdx.x;
    int tx = tid & 15, ty = tid >> 4;
    int m0 = blockIdx.x * 64;
    float acc[4][4] = {};
    for (int k0 = 0; k0 < DI_; k0 += 32) {
        #pragma unroll
        for (int i = 0; i < 2; i++) {
            int f4 = tid + i * 256;
            int row = f4 >> 3, kc = (f4 & 7) << 2;
            float4 v = *(const float4*)&g_xc[(size_t)(m0 + row) * DI_ + k0 + kc];
            As[kc][row] = v.x; As[kc + 1][row] = v.y; As[kc + 2][row] = v.z; As[kc + 3][row] = v.w;
        }
        #pragma unroll
        for (int i = 0; i < 8; i++) {
            int f = tid + i * 256;
            int kr = f >> 6, n = f & 63;
            Bs[kr][n] = (n < XPD) ? Wx[(size_t)(k0 + kr) * XPD + n] : 0.f;
        }
        __syncthreads();
        #pragma unroll
        for (int kk = 0; kk < 32; kk++) {
            float a[4], b[4];
            *(float4*)a = *(float4*)&As[kk][ty * 4];
            *(float4*)b = *(float4*)&Bs[kk][tx * 4];
            #pragma unroll
            for (int i = 0; i < 4; i++)
                #pragma unroll
                for (int j = 0; j < 4; j++)
                    acc[i][j] = fmaf(a[i], b[j], acc[i][j]);
        }
        __syncthreads();
    }
    #pragma unroll
    for (int i = 0; i < 4; i++) {
        int m = m0 + ty * 4 + i;
        #pragma unroll
        for (int j = 0; j < 4; j++) {
            int n = tx * 4 + j;
            if (n < XPD) g_xdbl[(size_t)m * XPD + n] = acc[i][j];
        }
    }
}

// dt = softplus(dt_r @ W_dt + dt_bias); block per token
__global__ void k_dt(const float* __restrict__ Wdt, const float* __restrict__ dtb) {
    int m = blockIdx.x;
    __shared__ float r[DTR_];
    if (threadIdx.x < DTR_) r[threadIdx.x] = g_xdbl[(size_t)m * XPD + threadIdx.x];
    __syncthreads();
    for (int di = threadIdx.x; di < DI_; di += 256) {
        float s = dtb[di];
        #pragma unroll
        for (int k = 0; k < DTR_; k++) s = fmaf(r[k], Wdt[k * DI_ + di], s);
        float sp = (s > 20.f) ? s : log1pf(__expf(s));
        g_dt[(size_t)m * DI_ + di] = sp;
    }
}

// Fused selective scan + Dskip + silu(z) gate + sum over time -> ybar[b,d]
// thread = (b, d, s); 16-lane group per channel. grid (48, 8) x 256.
__global__ void __launch_bounds__(256) k_scan(const float* __restrict__ A_log,
                                              const float* __restrict__ Dskip) {
    int b = blockIdx.y;
    int d = blockIdx.x * 16 + (threadIdx.x >> 4);
    int s = threadIdx.x & 15;
    float Aa = -expf(A_log[d * S_ + s]);
    float Dv = Dskip[d];
    const float* dtp = g_dt + (size_t)b * L_ * DI_ + d;
    const float* xcp = g_xc + (size_t)b * L_ * DI_ + d;
    const float* zsp = g_zs + (size_t)b * L_ * DI_ + d;
    const float* xd  = g_xdbl + (size_t)b * L_ * XPD;
    float h = 0.f, acc = 0.f;
    for (int t = 0; t < L_; t++) {
        float dtv = dtp[(size_t)t * DI_];
        float xcv = xcp[(size_t)t * DI_];
        float Bv  = xd[t * XPD + DTR_ + s];
        float Cv  = xd[t * XPD + DTR_ + S_ + s];
        float dA  = __expf(dtv * Aa);
        h = fmaf(dA, h, dtv * xcv * Bv);
        float y = h * Cv;
        y += __shfl_xor_sync(0xffffffffu, y, 8);
        y += __shfl_xor_sync(0xffffffffu, y, 4);
        y += __shfl_xor_sync(0xffffffffu, y, 2);
        y += __shfl_xor_sync(0xffffffffu, y, 1);
        if (s == 0) {
            float zv = zsp[(size_t)t * DI_];
            acc = fmaf(y + xcv * Dv, zv, acc);
        }
    }
    if (s == 0) g_ybar[b * DI_ + d] = acc;
}

// Head: pooled = xbar/L + (ybar/L)@W_out ; FC ; batchnorm(B) ; relu ; classifier
__global__ void __launch_bounds__(384) k_head(const float* __restrict__ Wout,
                                              const float* __restrict__ Wfc,
                                              const float* __restrict__ bfc,
                                              const float* __restrict__ gamma,
                                              const float* __restrict__ beta,
                                              const float* __restrict__ Wcls,
                                              const float* __restrict__ bcls,
                                              float* __restrict__ out) {
    __shared__ float ybm[B_ * DI_];      // 24 KB
    __shared__ float pooled[B_ * D_];    // 12 KB
    __shared__ float hbuf[B_ * 256];     // 8 KB
    int tid = threadIdx.x;
    const float invL = 1.f / (float)L_;
    for (int i = tid; i < B_ * DI_; i += 384) ybm[i] = g_ybar[i] * invL;
    __syncthreads();
    {   // pooled[b][d], d = tid
        int d = tid;
        float acc[B_] = {};
        for (int k = 0; k < DI_; k++) {
            float w = Wout[(size_t)k * D_ + d];
            #pragma unroll
            for (int b = 0; b < B_; b++) acc[b] = fmaf(ybm[b * DI_ + k], w, acc[b]);
        }
        #pragma unroll
        for (int b = 0; b < B_; b++) pooled[b * D_ + d] = g_xbar[b * D_ + d] * invL + acc[b];
    }
    __syncthreads();
    if (tid < 256) {
        int j = tid;
        float acc[B_] = {};
        for (int dd = 0; dd < D_; dd++) {
            float w = Wfc[dd * 256 + j];
            #pragma unroll
            for (int b = 0; b < B_; b++) acc[b] = fmaf(pooled[b * D_ + dd], w, acc[b]);
        }
        float mu = 0.f;
        #pragma unroll
        for (int b = 0; b < B_; b++) { acc[b] += bfc[j]; mu += acc[b]; }
        mu *= (1.f / B_);
        float var = 0.f;
        #pragma unroll
        for (int b = 0; b < B_; b++) { float dl = acc[b] - mu; var += dl * dl; }
        var *= (1.f / B_);
        float rs = rsqrtf(var + 1e-5f);
        #pragma unroll
        for (int b = 0; b < B_; b++) {
            float hv = (acc[b] - mu) * rs * gamma[j] + beta[j];
            hbuf[b * 256 + j] = hv > 0.f ? hv : 0.f;
        }
    }
    __syncthreads();
    if (tid < B_ * NC_) {
        int b = tid / NC_, c = tid % NC_;
        float s2 = bcls[c];
        for (int j = 0; j < 256; j++) s2 = fmaf(hbuf[b * 256 + j], Wcls[j * NC_ + c], s2);
        out[b * NC_ + c] = s2;
    }
}

// ---------------- launch ----------------
extern "C" void kernel_launch(void* const* d_in, const int* in_sizes, int n_in,
                              void* d_out, int out_size) {
    const float* x     = (const float*)d_in[0];
    const float* ln_w  = (const float*)d_in[1];
    const float* Win   = (const float*)d_in[2];
    const float* cw    = (const float*)d_in[3];
    const float* cb    = (const float*)d_in[4];
    const float* Wx    = (const float*)d_in[5];
    const float* Wdt   = (const float*)d_in[6];
    const float* dtb   = (const float*)d_in[7];
    const float* Alog  = (const float*)d_in[8];
    const float* Dsk   = (const float*)d_in[9];
    const float* Wout  = (const float*)d_in[10];
    const float* Wfc   = (const float*)d_in[11];
    const float* bfc   = (const float*)d_in[12];
    const float* gamma = (const float*)d_in[13];
    const float* beta  = (const float*)d_in[14];
    const float* Wcls  = (const float*)d_in[15];
    const float* bcls  = (const float*)d_in[16];
    float* out = (float*)d_out;

    k_zero_xbar<<<12, 256>>>();
    k_xbar<<<B_ * 64, D_>>>(x);
    k_rmsnorm<<<MTOK / 8, 256>>>(x, ln_w);
    k_gemm1<<<dim3(12, MTOK / 128), 256>>>(Win);
    k_conv<<<(MTOK * DI_) / 256, 256>>>(cw, cb);
    k_xproj<<<MTOK / 64, 256>>>(Wx);
    k_dt<<<MTOK, 256>>>(Wdt, dtb);
    k_scan<<<dim3(DI_ / 16, B_), 256>>>(Alog, Dsk);
    k_head<<<1, 384>>>(Wout, Wfc, bfc, gamma, beta, Wcls, bcls, out);
}

// round 6
// speedup vs baseline: 1.6185x; 1.6185x over previous
#include <cuda_runtime.h>
#include <cstdint>

// Problem constants
#define B_    8
#define L_    4096
#define D_    384
#define DI_   768
#define S_    16
#define DTR_  24
#define NC_   40
#define MTOK  (B_*L_)          // 32768
#define XPD   (DTR_ + 2*S_)    // 56
#define NCH   32               // scan chunks
#define TC    (L_/NCH)         // 128 steps per chunk

// ---------------- scratch (device globals; no allocation allowed) ----------------
__device__ float g_xn  [(size_t)MTOK * D_];    // rmsnormed x
__device__ float g_xp  [(size_t)MTOK * DI_];   // pre-conv branch
__device__ float g_zs  [(size_t)MTOK * DI_];   // silu(z)
__device__ float g_xc  [(size_t)MTOK * DI_];   // conv+silu
__device__ float g_xdbl[(size_t)MTOK * XPD];   // [dt_r | B | C]
__device__ float g_dt  [(size_t)MTOK * DI_];   // softplus dt
__device__ float g_xbar[B_ * D_];              // sum_l x
__device__ float g_ybar[B_ * DI_];             // sum_l y_final
// chunked-scan scratch
__device__ float g_hlT [(size_t)B_ * NCH * DI_ * S_];
__device__ float g_Pt  [(size_t)B_ * NCH * DI_ * S_];
__device__ float g_Gc  [(size_t)B_ * NCH * DI_ * S_];
__device__ float g_accl[(size_t)B_ * NCH * DI_];

// ---------------- kernels ----------------

__global__ void k_zero_xbar() {
    int i = blockIdx.x * blockDim.x + threadIdx.x;
    if (i < B_ * D_) g_xbar[i] = 0.f;
}

// partial sums of x over l (per (b,d)); grid = B*64 blocks x 384 threads
__global__ void k_xbar(const float* __restrict__ x) {
    int b  = blockIdx.x >> 6;
    int l0 = (blockIdx.x & 63) * 64;
    int d  = threadIdx.x;
    const float* p = x + ((size_t)(b * L_ + l0)) * D_ + d;
    float s = 0.f;
    #pragma unroll 8
    for (int i = 0; i < 64; i++) s += p[(size_t)i * D_];
    atomicAdd(&g_xbar[b * D_ + d], s);
}

// RMSNorm: warp per row; grid 4096 x 256
__global__ void k_rmsnorm(const float* __restrict__ x, const float* __restrict__ ln_w) {
    int row  = blockIdx.x * (blockDim.x >> 5) + (threadIdx.x >> 5);
    int lane = threadIdx.x & 31;
    const float* rp = x + (size_t)row * D_;
    float v[12]; float s = 0.f;
    #pragma unroll
    for (int i = 0; i < 12; i++) { v[i] = rp[lane + i * 32]; s += v[i] * v[i]; }
    #pragma unroll
    for (int o = 16; o; o >>= 1) s += __shfl_xor_sync(0xffffffffu, s, o);
    float r = rsqrtf(s * (1.f / D_) + 1e-5f);
    float* op = g_xn + (size_t)row * D_;
    #pragma unroll
    for (int i = 0; i < 12; i++) op[lane + i * 32] = v[i] * r * ln_w[lane + i * 32];
}

// GEMM1: g_xn[M,384] @ W_in[384,1536] -> xp (cols<768), silu-> zs (cols>=768)
__global__ void __launch_bounds__(256) k_gemm1(const float* __restrict__ Win) {
    __shared__ float As[16][128];
    __shared__ float Bs[16][128];
    int tid = threadIdx.x;
    int tx = tid & 15, ty = tid >> 4;
    int m0 = blockIdx.y * 128, n0 = blockIdx.x * 128;
    float acc[8][8] = {};
    for (int k0 = 0; k0 < D_; k0 += 16) {
        #pragma unroll
        for (int i = 0; i < 2; i++) {
            int f4 = tid + i * 256;
            int row = f4 >> 2, kc = (f4 & 3) << 2;
            float4 v = *(const float4*)&g_xn[(size_t)(m0 + row) * D_ + k0 + kc];
            As[kc][row] = v.x; As[kc + 1][row] = v.y; As[kc + 2][row] = v.z; As[kc + 3][row] = v.w;
        }
        #pragma unroll
        for (int i = 0; i < 2; i++) {
            int f4 = tid + i * 256;
            int kr = f4 >> 5, nc = (f4 & 31) << 2;
            *(float4*)&Bs[kr][nc] = *(const float4*)&Win[(size_t)(k0 + kr) * (2 * DI_) + n0 + nc];
        }
        __syncthreads();
        #pragma unroll
        for (int kk = 0; kk < 16; kk++) {
            float a[8], b[8];
            *(float4*)(a)     = *(float4*)&As[kk][ty * 8];
            *(float4*)(a + 4) = *(float4*)&As[kk][ty * 8 + 4];
            *(float4*)(b)     = *(float4*)&Bs[kk][tx * 8];
            *(float4*)(b + 4) = *(float4*)&Bs[kk][tx * 8 + 4];
            #pragma unroll
            for (int i = 0; i < 8; i++)
                #pragma unroll
                for (int j = 0; j < 8; j++)
                    acc[i][j] = fmaf(a[i], b[j], acc[i][j]);
        }
        __syncthreads();
    }
    #pragma unroll
    for (int i = 0; i < 8; i++) {
        int m = m0 + ty * 8 + i;
        #pragma unroll
        for (int j = 0; j < 8; j++) {
            int n = n0 + tx * 8 + j;
            float v = acc[i][j];
            if (n < DI_) {
                g_xp[(size_t)m * DI_ + n] = v;
            } else {
                float sg = 1.f / (1.f + __expf(-v));
                g_zs[(size_t)m * DI_ + (n - DI_)] = v * sg;
            }
        }
    }
}

// causal depthwise conv K=4 + silu
__global__ void k_conv(const float* __restrict__ cw, const float* __restrict__ cb) {
    int idx = blockIdx.x * 256 + threadIdx.x;   // (b*L+l)*DI + di
    int di = idx % DI_;
    int ml = idx / DI_;
    int l  = ml & (L_ - 1);
    float w0 = cw[di * 4], w1 = cw[di * 4 + 1], w2 = cw[di * 4 + 2], w3 = cw[di * 4 + 3];
    const float* p = g_xp + (size_t)ml * DI_ + di;
    float s = cb[di] + w3 * p[0];
    if (l >= 1) s = fmaf(w2, p[-DI_], s);
    if (l >= 2) s = fmaf(w1, p[-2 * DI_], s);
    if (l >= 3) s = fmaf(w0, p[-3 * DI_], s);
    float sg = 1.f / (1.f + __expf(-s));
    g_xc[(size_t)ml * DI_ + di] = s * sg;
}

// x_dbl = xc[M,768] @ W_xproj[768,56]
__global__ void __launch_bounds__(256) k_xproj(const float* __restrict__ Wx) {
    __shared__ float As[32][64];
    __shared__ float Bs[32][64];
    int tid = threadIdx.x;
    int tx = tid & 15, ty = tid >> 4;
    int m0 = blockIdx.x * 64;
    float acc[4][4] = {};
    for (int k0 = 0; k0 < DI_; k0 += 32) {
        #pragma unroll
        for (int i = 0; i < 2; i++) {
            int f4 = tid + i * 256;
            int row = f4 >> 3, kc = (f4 & 7) << 2;
            float4 v = *(const float4*)&g_xc[(size_t)(m0 + row) * DI_ + k0 + kc];
            As[kc][row] = v.x; As[kc + 1][row] = v.y; As[kc + 2][row] = v.z; As[kc + 3][row] = v.w;
        }
        #pragma unroll
        for (int i = 0; i < 8; i++) {
            int f = tid + i * 256;
            int kr = f >> 6, n = f & 63;
            Bs[kr][n] = (n < XPD) ? Wx[(size_t)(k0 + kr) * XPD + n] : 0.f;
        }
        __syncthreads();
        #pragma unroll
        for (int kk = 0; kk < 32; kk++) {
            float a[4], b[4];
            *(float4*)a = *(float4*)&As[kk][ty * 4];
            *(float4*)b = *(float4*)&Bs[kk][tx * 4];
            #pragma unroll
            for (int i = 0; i < 4; i++)
                #pragma unroll
                for (int j = 0; j < 4; j++)
                    acc[i][j] = fmaf(a[i], b[j], acc[i][j]);
        }
        __syncthreads();
    }
    #pragma unroll
    for (int i = 0; i < 4; i++) {
        int m = m0 + ty * 4 + i;
        #pragma unroll
        for (int j = 0; j < 4; j++) {
            int n = tx * 4 + j;
            if (n < XPD) g_xdbl[(size_t)m * XPD + n] = acc[i][j];
        }
    }
}

// dt = softplus(dt_r @ W_dt + dt_bias)
// Tiled: block = 128 tokens x 256 channels; W_dt column slice in registers,
// dt_r broadcast from smem. grid (MTOK/128, DI/256).
__global__ void __launch_bounds__(256) k_dt(const float* __restrict__ Wdt,
                                            const float* __restrict__ dtb) {
    __shared__ float sR[128][DTR_];
    int tok0 = blockIdx.x * 128;
    int di   = blockIdx.y * 256 + threadIdx.x;
    for (int i = threadIdx.x; i < 128 * DTR_; i += 256) {
        int r = i / DTR_, k = i % DTR_;
        sR[r][k] = g_xdbl[(size_t)(tok0 + r) * XPD + k];
    }
    float w[DTR_];
    #pragma unroll
    for (int k = 0; k < DTR_; k++) w[k] = Wdt[k * DI_ + di];
    float bias = dtb[di];
    __syncthreads();
    for (int t = 0; t < 128; t++) {
        float s = bias;
        #pragma unroll
        for (int k = 0; k < DTR_; k++) s = fmaf(sR[t][k], w[k], s);
        float sp = (s > 20.f) ? s : __logf(1.f + __expf(s));
        g_dt[(size_t)(tok0 + t) * DI_ + di] = sp;
    }
}

// ---- Chunked selective scan ----
// Kernel A: per (b, d, chunk), states split 8/8 across lane halves (lane^16 pair).
// Computes local scan hl, running product P, correction G_s = sum_t z_t C_{t,s} P_{t,s},
// and local gated accumulation. grid (DI/256, NCH, B), block 512.
__global__ void __launch_bounds__(512) k_scanA(const float* __restrict__ A_log,
                                               const float* __restrict__ Dskip) {
    int b = blockIdx.z, c = blockIdx.y;
    int w = threadIdx.x >> 5, lane = threadIdx.x & 31;
    int half = lane >> 4;
    int d = blockIdx.x * 256 + w * 16 + (lane & 15);
    __shared__ float sB[TC][S_];
    __shared__ float sC[TC][S_];
    const float* xd = g_xdbl + ((size_t)(b * L_ + c * TC)) * XPD + DTR_;
    for (int i = threadIdx.x; i < TC * 32; i += 512) {
        int t = i >> 5, j = i & 31;
        float v = xd[(size_t)t * XPD + j];
        if (j < S_) sB[t][j] = v; else sC[t][j - S_] = v;
    }
    __syncthreads();

    float Aa[8], hl[8], P[8], G[8];
    #pragma unroll
    for (int s = 0; s < 8; s++) {
        Aa[s] = -__expf(A_log[d * S_ + half * 8 + s]);
        hl[s] = 0.f; P[s] = 1.f; G[s] = 0.f;
    }
    float Dv = Dskip[d];
    float accl = 0.f;
    size_t base = ((size_t)(b * L_ + c * TC)) * DI_ + d;
    for (int t = 0; t < TC; t++) {
        float dtv = g_dt[base + (size_t)t * DI_];
        float xcv = g_xc[base + (size_t)t * DI_];
        float zsv = g_zs[base + (size_t)t * DI_];
        float du  = dtv * xcv;
        float yl  = 0.f;
        #pragma unroll
        for (int s = 0; s < 8; s++) {
            float Bv = sB[t][half * 8 + s];
            float Cv = sC[t][half * 8 + s];
            float dA = __expf(dtv * Aa[s]);
            P[s] *= dA;
            hl[s] = fmaf(dA, hl[s], du * Bv);
            yl    = fmaf(hl[s], Cv, yl);
            G[s]  = fmaf(zsv * Cv, P[s], G[s]);
        }
        yl += __shfl_xor_sync(0xffffffffu, yl, 16);
        if (half == 0) accl = fmaf(yl + xcv * Dv, zsv, accl);
    }
    size_t o = (((size_t)(b * NCH + c) * DI_) + d) * S_ + half * 8;
    #pragma unroll
    for (int s = 0; s < 8; s += 4) {
        *(float4*)&g_hlT[o + s] = make_float4(hl[s], hl[s+1], hl[s+2], hl[s+3]);
        *(float4*)&g_Pt [o + s] = make_float4(P[s],  P[s+1],  P[s+2],  P[s+3]);
        *(float4*)&g_Gc [o + s] = make_float4(G[s],  G[s+1],  G[s+2],  G[s+3]);
    }
    if (half == 0) g_accl[((size_t)(b * NCH + c)) * DI_ + d] = accl;
}

// Kernel B: sequential over the 32 chunks; thread per (b,d).
__global__ void k_scanB() {
    int idx = blockIdx.x * 256 + threadIdx.x;   // B_*DI_ threads
    int b = idx / DI_, d = idx % DI_;
    float h[S_];
    #pragma unroll
    for (int s = 0; s < S_; s++) h[s] = 0.f;
    float acc = 0.f;
    for (int c = 0; c < NCH; c++) {
        size_t o = (((size_t)(b * NCH + c) * DI_) + d) * S_;
        acc += g_accl[((size_t)(b * NCH + c)) * DI_ + d];
        #pragma unroll
        for (int s = 0; s < S_; s += 4) {
            float4 Gv = *(const float4*)&g_Gc [o + s];
            float4 Pv = *(const float4*)&g_Pt [o + s];
            float4 Hv = *(const float4*)&g_hlT[o + s];
            acc = fmaf(Gv.x, h[s  ], acc); h[s  ] = fmaf(Pv.x, h[s  ], Hv.x);
            acc = fmaf(Gv.y, h[s+1], acc); h[s+1] = fmaf(Pv.y, h[s+1], Hv.y);
            acc = fmaf(Gv.z, h[s+2], acc); h[s+2] = fmaf(Pv.z, h[s+2], Hv.z);
            acc = fmaf(Gv.w, h[s+3], acc); h[s+3] = fmaf(Pv.w, h[s+3], Hv.w);
        }
    }
    g_ybar[b * DI_ + d] = acc;
}

// Head: pooled = xbar/L + (ybar/L)@W_out ; FC ; batchnorm(B) ; relu ; classifier
__global__ void __launch_bounds__(384) k_head(const float* __restrict__ Wout,
                                              const float* __restrict__ Wfc,
                                              const float* __restrict__ bfc,
                                              const float* __restrict__ gamma,
                                              const float* __restrict__ beta,
                                              const float* __restrict__ Wcls,
                                              const float* __restrict__ bcls,
                                              float* __restrict__ out) {
    __shared__ float ybm[B_ * DI_];
    __shared__ float pooled[B_ * D_];
    __shared__ float hbuf[B_ * 256];
    int tid = threadIdx.x;
    const float invL = 1.f / (float)L_;
    for (int i = tid; i < B_ * DI_; i += 384) ybm[i] = g_ybar[i] * invL;
    __syncthreads();
    {
        int d = tid;
        float acc[B_] = {};
        for (int k = 0; k < DI_; k++) {
            float w = Wout[(size_t)k * D_ + d];
            #pragma unroll
            for (int b = 0; b < B_; b++) acc[b] = fmaf(ybm[b * DI_ + k], w, acc[b]);
        }
        #pragma unroll
        for (int b = 0; b < B_; b++) pooled[b * D_ + d] = g_xbar[b * D_ + d] * invL + acc[b];
    }
    __syncthreads();
    if (tid < 256) {
        int j = tid;
        float acc[B_] = {};
        for (int dd = 0; dd < D_; dd++) {
            float w = Wfc[dd * 256 + j];
            #pragma unroll
            for (int b = 0; b < B_; b++) acc[b] = fmaf(pooled[b * D_ + dd], w, acc[b]);
        }
        float mu = 0.f;
        #pragma unroll
        for (int b = 0; b < B_; b++) { acc[b] += bfc[j]; mu += acc[b]; }
        mu *= (1.f / B_);
        float var = 0.f;
        #pragma unroll
        for (int b = 0; b < B_; b++) { float dl = acc[b] - mu; var += dl * dl; }
        var *= (1.f / B_);
        float rs = rsqrtf(var + 1e-5f);
        #pragma unroll
        for (int b = 0; b < B_; b++) {
            float hv = (acc[b] - mu) * rs * gamma[j] + beta[j];
            hbuf[b * 256 + j] = hv > 0.f ? hv : 0.f;
        }
    }
    __syncthreads();
    if (tid < B_ * NC_) {
        int b = tid / NC_, c = tid % NC_;
        float s2 = bcls[c];
        for (int j = 0; j < 256; j++) s2 = fmaf(hbuf[b * 256 + j], Wcls[j * NC_ + c], s2);
        out[b * NC_ + c] = s2;
    }
}

// ---------------- launch ----------------
extern "C" void kernel_launch(void* const* d_in, const int* in_sizes, int n_in,
                              void* d_out, int out_size) {
    const float* x     = (const float*)d_in[0];
    const float* ln_w  = (const float*)d_in[1];
    const float* Win   = (const float*)d_in[2];
    const float* cw    = (const float*)d_in[3];
    const float* cb    = (const float*)d_in[4];
    const float* Wx    = (const float*)d_in[5];
    const float* Wdt   = (const float*)d_in[6];
    const float* dtb   = (const float*)d_in[7];
    const float* Alog  = (const float*)d_in[8];
    const float* Dsk   = (const float*)d_in[9];
    const float* Wout  = (const float*)d_in[10];
    const float* Wfc   = (const float*)d_in[11];
    const float* bfc   = (const float*)d_in[12];
    const float* gamma = (const float*)d_in[13];
    const float* beta  = (const float*)d_in[14];
    const float* Wcls  = (const float*)d_in[15];
    const float* bcls  = (const float*)d_in[16];
    float* out = (float*)d_out;

    k_zero_xbar<<<12, 256>>>();
    k_xbar<<<B_ * 64, D_>>>(x);
    k_rmsnorm<<<MTOK / 8, 256>>>(x, ln_w);
    k_gemm1<<<dim3(12, MTOK / 128), 256>>>(Win);
    k_conv<<<(MTOK * DI_) / 256, 256>>>(cw, cb);
    k_xproj<<<MTOK / 64, 256>>>(Wx);
    k_dt<<<dim3(MTOK / 128, DI_ / 256), 256>>>(Wdt, dtb);
    k_scanA<<<dim3(DI_ / 256, NCH, B_), 512>>>(Alog, Dsk);
    k_scanB<<<(B_ * DI_) / 256, 256>>>();
    k_head<<<1, 384>>>(Wout, Wfc, bfc, gamma, beta, Wcls, bcls, out);
}